// round 15
// baseline (speedup 1.0000x reference)
#include <cuda_runtime.h>

#define IH 384
#define IW 384
#define HO 382
#define WO 382
#define NB 8
#define HALOY 6
#define HALOX 8
#define BROWS 16       // pixel rows per block
#define TH 30          // rows [ho0-6, ho0+23]
#define TW 48          // cols [wo0-8, wo0+39], 12 float4 per row, 16B-aligned
#define TILE_CH (TH * TW)   // 1440

typedef unsigned long long u64;

__device__ __forceinline__ u64 fma2(u64 a, u64 b, u64 c) {
    u64 d;
    asm("fma.rn.f32x2 %0, %1, %2, %3;" : "=l"(d) : "l"(a), "l"(b), "l"(c));
    return d;
}
__device__ __forceinline__ u64 add2(u64 a, u64 b) {
    u64 d;
    asm("add.rn.f32x2 %0, %1, %2;" : "=l"(d) : "l"(a), "l"(b));
    return d;
}
__device__ __forceinline__ u64 pack2(float lo, float hi) {
    u64 r;
    asm("mov.b64 %0, {%1, %2};" : "=l"(r) : "f"(lo), "f"(hi));
    return r;
}
__device__ __forceinline__ void unpack2(u64 v, float& lo, float& hi) {
    asm("mov.b64 {%0, %1}, %2;" : "=f"(lo), "=f"(hi) : "l"(v));
}

struct __align__(16) WPack {
    u64 w1p[9 * 28];   // [kk][j] packed (wdy, wdx); slot 27 = 0 pad; 224B/kk
    u64 b1p[9];        // packed (b_dy, b_dx)
    u64 pad1;
    u64 w2d[9 * 10];   // [kk][c*3+o] = dup(w2[o][c][kk]); slot 9 = 0 pad
    u64 b2d[3];        // dup(b2[o])
    u64 pad2;
};

__device__   WPack g_pack;
__constant__ WPack c_pack;

__global__ void pack_weights(const float* __restrict__ w1,
                             const float* __restrict__ b1,
                             const float* __restrict__ w2,
                             const float* __restrict__ b2)
{
    int i = threadIdx.x;
    if (i < 9 * 27) {
        int kk = i / 27, j = i % 27;
        g_pack.w1p[kk * 28 + j] = pack2(w1[(2 * kk) * 27 + j], w1[(2 * kk + 1) * 27 + j]);
    }
    if (i < 9) {
        g_pack.w1p[i * 28 + 27] = 0ull;
        g_pack.b1p[i] = pack2(b1[2 * i], b1[2 * i + 1]);
        g_pack.w2d[i * 10 + 9] = 0ull;
    }
    if (i < 81) {
        int kk = i / 9, r = i % 9;
        int c = r / 3, o = r % 3;
        float v = w2[o * 27 + c * 9 + kk];
        g_pack.w2d[kk * 10 + c * 3 + o] = pack2(v, v);
    }
    if (i < 3) { float v = b2[i]; g_pack.b2d[i] = pack2(v, v); }
    if (i == 0) { g_pack.pad1 = 0ull; g_pack.pad2 = 0ull; }
}

__global__ __launch_bounds__(256, 3)
void deform_fused15(const float* __restrict__ x,
                    float* __restrict__ out)
{
    __shared__ __align__(16) float s_tile[3 * TILE_CH];

    const int tid = threadIdx.y * 32 + threadIdx.x;

    const int wo0 = blockIdx.x * 32;
    const int ho0 = blockIdx.y * BROWS;
    const int b   = blockIdx.z;
    const float* __restrict__ xb = x + (size_t)b * 3 * IH * IW;

    const int rowBase = ho0 - HALOY;
    const int colBase = wo0 - HALOX;   // divisible by 4 -> 16B aligned

    // ---- input tile to shared, vectorized float4 (zero-filled outside image) ----
    // 3 ch x 30 rows x 12 float4 = 1080 vector slots
    for (int i = tid; i < 3 * TH * (TW / 4); i += 256) {
        int c  = i / (TH * (TW / 4));
        int rr = i - c * (TH * (TW / 4));
        int r  = rr / (TW / 4);
        int q  = rr - r * (TW / 4);
        int gy  = rowBase + r;
        int gx0 = colBase + 4 * q;
        float4 v = make_float4(0.f, 0.f, 0.f, 0.f);
        if ((unsigned)gy < IH) {
            const float* rp = xb + ((size_t)c * IH + gy) * IW;
            if (gx0 >= 0 && gx0 + 3 < IW) {
                v = __ldg((const float4*)(rp + gx0));   // aligned LDG.128
            } else {
                float t0 = ((unsigned)(gx0 + 0) < IW) ? __ldg(rp + gx0 + 0) : 0.f;
                float t1 = ((unsigned)(gx0 + 1) < IW) ? __ldg(rp + gx0 + 1) : 0.f;
                float t2 = ((unsigned)(gx0 + 2) < IW) ? __ldg(rp + gx0 + 2) : 0.f;
                float t3 = ((unsigned)(gx0 + 3) < IW) ? __ldg(rp + gx0 + 3) : 0.f;
                v = make_float4(t0, t1, t2, t3);
            }
        }
        *(float4*)&s_tile[c * TILE_CH + r * TW + 4 * q] = v;   // STS.128
    }
    __syncthreads();

    const int wo  = wo0 + threadIdx.x;
    const int hoA = ho0 + 2 * threadIdx.y;   // pixel pair rows hoA, hoA+1 (ty 0..7)
    const int ltx = threadIdx.x + HALOX;
    const int lty = 2 * threadIdx.y + HALOY;

    // ---- window (4 rows x 3 cols x 3 ch) duplicated-packed in registers ----
    u64 wr2[3][4][3];
#pragma unroll
    for (int c = 0; c < 3; c++)
#pragma unroll
        for (int r = 0; r < 4; r++)
#pragma unroll
            for (int kw = 0; kw < 3; kw++) {
                float v = s_tile[c * TILE_CH + (lty + r) * TW + (ltx + kw)];
                wr2[c][r][kw] = pack2(v, v);
            }

    // packed (p0, p1) accumulators per output channel
    u64 accp[3];
#pragma unroll
    for (int o = 0; o < 3; o++) accp[o] = c_pack.b2d[o];

#pragma unroll 3
    for (int kk = 0; kk < 9; kk++) {
        // ---- offset conv: weights via LDCU.128 (paired), 4 independent FFMA2 chains ----
        u64 a0a = c_pack.b1p[kk];
        u64 a1a = a0a;
        u64 a0b = pack2(0.f, 0.f);
        u64 a1b = a0b;
        const ulonglong2* __restrict__ wq = (const ulonglong2*)&c_pack.w1p[kk * 28];
#pragma unroll
        for (int jj = 0; jj < 14; jj++) {
            ulonglong2 w = wq[jj];
            {
                const int j = 2 * jj;
                const int c = j / 9, kh = (j / 3) % 3, kw = j % 3;
                a0a = fma2(wr2[c][kh][kw],     w.x, a0a);
                a1a = fma2(wr2[c][kh + 1][kw], w.x, a1a);
            }
            {
                const int j2 = 2 * jj + 1;
                const int j = (j2 < 27) ? j2 : 0;   // slot 27 is the zero weight: adds 0
                const int c = j / 9, kh = (j / 3) % 3, kw = j % 3;
                a0b = fma2(wr2[c][kh][kw],     w.y, a0b);
                a1b = fma2(wr2[c][kh + 1][kw], w.y, a1b);
            }
        }
        u64 a0 = add2(a0a, a0b);
        u64 a1 = add2(a1a, a1b);

        const int kh = kk / 3;
        const int kw = kk - 3 * kh;

        // dup'd w2 for this kk via LDCU.128 (paired loads cover 9 weights + pad)
        u64 w2v[9];
        {
            const ulonglong2* __restrict__ w2q = (const ulonglong2*)&c_pack.w2d[kk * 10];
            ulonglong2 t0 = w2q[0], t1 = w2q[1], t2 = w2q[2], t3 = w2q[3];
            w2v[0] = t0.x; w2v[1] = t0.y;
            w2v[2] = t1.x; w2v[3] = t1.y;
            w2v[4] = t2.x; w2v[5] = t2.y;
            w2v[6] = t3.x; w2v[7] = t3.y;
            w2v[8] = c_pack.w2d[kk * 10 + 8];
        }

        float vch[2][3];
#pragma unroll
        for (int p = 0; p < 2; p++) {
            float dy, dx;
            unpack2(p ? a1 : a0, dy, dx);
            float py = (float)(hoA + p + kh) + dy;
            float px = (float)(wo + kw) + dx;
            int y0 = __float2int_rd(py);
            int x0 = __float2int_rd(px);
            float wy = py - (float)y0;
            float wx = px - (float)x0;

            float c00 = (1.f - wy) * (1.f - wx);
            float c01 = (1.f - wy) * wx;
            float c10 = wy * (1.f - wx);
            float c11 = wy * wx;

            int ly0 = y0 - rowBase;
            int lx0 = x0 - colBase;

            if ((unsigned)ly0 <= TH - 2 && (unsigned)lx0 <= TW - 2) {
                // fast path: zero-filled tile makes validity masks redundant
                int t = ly0 * TW + lx0;
                {
                    const float* __restrict__ tc = &s_tile[t];
                    vch[p][0] = fmaf(c11, tc[TW + 1], fmaf(c10, tc[TW], fmaf(c01, tc[1], c00 * tc[0])));
                }
                {
                    const float* __restrict__ tc = &s_tile[TILE_CH + t];
                    vch[p][1] = fmaf(c11, tc[TW + 1], fmaf(c10, tc[TW], fmaf(c01, tc[1], c00 * tc[0])));
                }
                {
                    const float* __restrict__ tc = &s_tile[2 * TILE_CH + t];
                    vch[p][2] = fmaf(c11, tc[TW + 1], fmaf(c10, tc[TW], fmaf(c01, tc[1], c00 * tc[0])));
                }
            } else {
                // rare slow path: clamped global loads (exact reference semantics)
                bool vy0 = (y0 >= 0)  && (y0 <= IH - 1);
                bool vy1 = (y0 >= -1) && (y0 <= IH - 2);
                bool vx0 = (x0 >= 0)  && (x0 <= IW - 1);
                bool vx1 = (x0 >= -1) && (x0 <= IW - 2);
                float m00 = c00 * ((vy0 && vx0) ? 1.f : 0.f);
                float m01 = c01 * ((vy0 && vx1) ? 1.f : 0.f);
                float m10 = c10 * ((vy1 && vx0) ? 1.f : 0.f);
                float m11 = c11 * ((vy1 && vx1) ? 1.f : 0.f);
                int yc0 = min(max(y0, 0), IH - 1);
                int yc1 = min(max(y0 + 1, 0), IH - 1);
                int xc0 = min(max(x0, 0), IW - 1);
                int xc1 = min(max(x0 + 1, 0), IW - 1);
                int i00 = yc0 * IW + xc0;
                int i01 = yc0 * IW + xc1;
                int i10 = yc1 * IW + xc0;
                int i11 = yc1 * IW + xc1;
#pragma unroll
                for (int c = 0; c < 3; c++) {
                    const float* __restrict__ xc = xb + (size_t)c * IH * IW;
                    vch[p][c] = m00 * __ldg(xc + i00) + m01 * __ldg(xc + i01)
                              + m10 * __ldg(xc + i10) + m11 * __ldg(xc + i11);
                }
            }
        }

        // ---- packed einsum: acc[o] += dup(w2[o][c][kk]) * (v_p0, v_p1) ----
#pragma unroll
        for (int c = 0; c < 3; c++) {
            u64 vp = pack2(vch[0][c], vch[1][c]);
            accp[0] = fma2(w2v[c * 3 + 0], vp, accp[0]);
            accp[1] = fma2(w2v[c * 3 + 1], vp, accp[1]);
            accp[2] = fma2(w2v[c * 3 + 2], vp, accp[2]);
        }
    }

    // ---- store ----
    if (wo < WO) {
        const size_t plane = (size_t)HO * WO;
        const size_t base  = (size_t)b * 3 * plane + (size_t)hoA * WO + wo;
        float a0, a1;
#pragma unroll
        for (int o = 0; o < 3; o++) {
            unpack2(accp[o], a0, a1);
            if (hoA < HO)     out[base + o * plane]      = a0;
            if (hoA + 1 < HO) out[base + o * plane + WO] = a1;
        }
    }
}

extern "C" void kernel_launch(void* const* d_in, const int* in_sizes, int n_in,
                              void* d_out, int out_size)
{
    const float* x  = (const float*)d_in[0];
    const float* w1 = (const float*)d_in[1];
    const float* b1 = (const float*)d_in[2];
    const float* w2 = (const float*)d_in[3];
    const float* b2 = (const float*)d_in[4];
    float* out = (float*)d_out;

    // 1) pack weights into __device__ scratch
    pack_weights<<<1, 256>>>(w1, b1, w2, b2);

    // 2) install into __constant__ (device-to-device async copy; graph-capturable)
    void* gaddr = nullptr;
    cudaGetSymbolAddress(&gaddr, g_pack);
    cudaMemcpyToSymbolAsync(c_pack, gaddr, sizeof(WPack), 0,
                            cudaMemcpyDeviceToDevice, 0);

    // 3) main kernel
    dim3 block(32, 8, 1);
    dim3 grid((WO + 31) / 32, (HO + BROWS - 1) / BROWS, NB);
    deform_fused15<<<grid, block>>>(x, out);
}

// round 16
// speedup vs baseline: 1.0740x; 1.0740x over previous
#include <cuda_runtime.h>

#define IH 384
#define IW 384
#define HO 382
#define WO 382
#define NB 8
#define HALOY 6
#define HALOX 8
#define BROWS 16       // pixel rows per block
#define TH 30          // rows [ho0-6, ho0+23]
#define TW 48          // cols [wo0-8, wo0+39], 12 float4 per row, 16B-aligned
#define TILE_CH (TH * TW)   // 1440

typedef unsigned long long u64;

__device__ __forceinline__ u64 fma2(u64 a, u64 b, u64 c) {
    u64 d;
    asm("fma.rn.f32x2 %0, %1, %2, %3;" : "=l"(d) : "l"(a), "l"(b), "l"(c));
    return d;
}
__device__ __forceinline__ u64 add2(u64 a, u64 b) {
    u64 d;
    asm("add.rn.f32x2 %0, %1, %2;" : "=l"(d) : "l"(a), "l"(b));
    return d;
}
__device__ __forceinline__ u64 pack2(float lo, float hi) {
    u64 r;
    asm("mov.b64 %0, {%1, %2};" : "=l"(r) : "f"(lo), "f"(hi));
    return r;
}
__device__ __forceinline__ void unpack2(u64 v, float& lo, float& hi) {
    asm("mov.b64 {%0, %1}, %2;" : "=f"(lo), "=f"(hi) : "l"(v));
}

struct __align__(16) WPack {
    u64 w1p[9 * 28];   // [kk][j] packed (wdy, wdx); slot 27 = 0 pad; 224B/kk
    u64 b1p[9];        // packed (b_dy, b_dx)
    u64 pad1;
    u64 w2d[9 * 10];   // [kk][c*3+o] = dup(w2[o][c][kk]); slot 9 = 0 pad
    u64 b2d[3];        // dup(b2[o])
    u64 pad2;
};

__device__   WPack g_pack;
__constant__ WPack c_pack;

__global__ void pack_weights(const float* __restrict__ w1,
                             const float* __restrict__ b1,
                             const float* __restrict__ w2,
                             const float* __restrict__ b2)
{
    int i = threadIdx.x;
    if (i < 9 * 27) {
        int kk = i / 27, j = i % 27;
        g_pack.w1p[kk * 28 + j] = pack2(w1[(2 * kk) * 27 + j], w1[(2 * kk + 1) * 27 + j]);
    }
    if (i < 9) {
        g_pack.w1p[i * 28 + 27] = 0ull;
        g_pack.b1p[i] = pack2(b1[2 * i], b1[2 * i + 1]);
        g_pack.w2d[i * 10 + 9] = 0ull;
    }
    if (i < 81) {
        int kk = i / 9, r = i % 9;
        int c = r / 3, o = r % 3;
        float v = w2[o * 27 + c * 9 + kk];
        g_pack.w2d[kk * 10 + c * 3 + o] = pack2(v, v);
    }
    if (i < 3) { float v = b2[i]; g_pack.b2d[i] = pack2(v, v); }
    if (i == 0) { g_pack.pad1 = 0ull; g_pack.pad2 = 0ull; }
}

__global__ __launch_bounds__(256, 3)
void deform_fused16(const float* __restrict__ x,
                    float* __restrict__ out)
{
    __shared__ __align__(16) float s_tile[3 * TILE_CH];

    const int tid = threadIdx.y * 32 + threadIdx.x;

    const int wo0 = blockIdx.x * 32;
    const int ho0 = blockIdx.y * BROWS;
    const int b   = blockIdx.z;
    const float* __restrict__ xb = x + (size_t)b * 3 * IH * IW;

    const int rowBase = ho0 - HALOY;
    const int colBase = wo0 - HALOX;   // divisible by 4 -> 16B aligned

    // ---- input tile to shared, vectorized float4 (zero-filled outside image) ----
    for (int i = tid; i < 3 * TH * (TW / 4); i += 256) {
        int c  = i / (TH * (TW / 4));
        int rr = i - c * (TH * (TW / 4));
        int r  = rr / (TW / 4);
        int q  = rr - r * (TW / 4);
        int gy  = rowBase + r;
        int gx0 = colBase + 4 * q;
        float4 v = make_float4(0.f, 0.f, 0.f, 0.f);
        if ((unsigned)gy < IH) {
            const float* rp = xb + ((size_t)c * IH + gy) * IW;
            if (gx0 >= 0 && gx0 + 3 < IW) {
                v = __ldg((const float4*)(rp + gx0));   // aligned LDG.128
            } else {
                float t0 = ((unsigned)(gx0 + 0) < IW) ? __ldg(rp + gx0 + 0) : 0.f;
                float t1 = ((unsigned)(gx0 + 1) < IW) ? __ldg(rp + gx0 + 1) : 0.f;
                float t2 = ((unsigned)(gx0 + 2) < IW) ? __ldg(rp + gx0 + 2) : 0.f;
                float t3 = ((unsigned)(gx0 + 3) < IW) ? __ldg(rp + gx0 + 3) : 0.f;
                v = make_float4(t0, t1, t2, t3);
            }
        }
        *(float4*)&s_tile[c * TILE_CH + r * TW + 4 * q] = v;   // STS.128
    }
    __syncthreads();

    const int wo  = wo0 + threadIdx.x;
    const int hoA = ho0 + 2 * threadIdx.y;   // pixel pair rows hoA, hoA+1 (ty 0..7)
    const int ltx = threadIdx.x + HALOX;
    const int lty = 2 * threadIdx.y + HALOY;

    // float coordinate bases (hoisted I2F)
    const float hofp[2] = { (float)hoA, (float)hoA + 1.f };
    const float wof     = (float)wo;

    // ---- window (4 rows x 3 cols x 3 ch) duplicated-packed in registers ----
    u64 wr2[3][4][3];
#pragma unroll
    for (int c = 0; c < 3; c++)
#pragma unroll
        for (int r = 0; r < 4; r++)
#pragma unroll
            for (int kw = 0; kw < 3; kw++) {
                float v = s_tile[c * TILE_CH + (lty + r) * TW + (ltx + kw)];
                wr2[c][r][kw] = pack2(v, v);
            }

    // packed (p0, p1) accumulators per output channel
    u64 accp[3];
#pragma unroll
    for (int o = 0; o < 3; o++) accp[o] = c_pack.b2d[o];

#pragma unroll
    for (int kk = 0; kk < 9; kk++) {
        // ---- offset conv: weights via LDCU.128 (paired), 4 independent FFMA2 chains ----
        u64 a0a = c_pack.b1p[kk];
        u64 a1a = a0a;
        u64 a0b = pack2(0.f, 0.f);
        u64 a1b = a0b;
        const ulonglong2* __restrict__ wq = (const ulonglong2*)&c_pack.w1p[kk * 28];
#pragma unroll
        for (int jj = 0; jj < 14; jj++) {
            ulonglong2 w = wq[jj];
            {
                const int j = 2 * jj;
                const int c = j / 9, kh = (j / 3) % 3, kw = j % 3;
                a0a = fma2(wr2[c][kh][kw],     w.x, a0a);
                a1a = fma2(wr2[c][kh + 1][kw], w.x, a1a);
            }
            {
                const int j2 = 2 * jj + 1;
                const int j = (j2 < 27) ? j2 : 0;   // slot 27 is the zero weight: adds 0
                const int c = j / 9, kh = (j / 3) % 3, kw = j % 3;
                a0b = fma2(wr2[c][kh][kw],     w.y, a0b);
                a1b = fma2(wr2[c][kh + 1][kw], w.y, a1b);
            }
        }
        u64 a0 = add2(a0a, a0b);
        u64 a1 = add2(a1a, a1b);

        const int kh = kk / 3;
        const int kw = kk - 3 * kh;
        const float khf = (float)kh;   // compile-time under full unroll
        const float kwf = (float)kw;

        // dup'd w2 for this kk via LDCU.128 (paired loads cover 9 weights + pad)
        u64 w2v[9];
        {
            const ulonglong2* __restrict__ w2q = (const ulonglong2*)&c_pack.w2d[kk * 10];
            ulonglong2 t0 = w2q[0], t1 = w2q[1], t2 = w2q[2], t3 = w2q[3];
            w2v[0] = t0.x; w2v[1] = t0.y;
            w2v[2] = t1.x; w2v[3] = t1.y;
            w2v[4] = t2.x; w2v[5] = t2.y;
            w2v[6] = t3.x; w2v[7] = t3.y;
            w2v[8] = c_pack.w2d[kk * 10 + 8];
        }

        float vch[2][3];
#pragma unroll
        for (int p = 0; p < 2; p++) {
            float dy, dx;
            unpack2(p ? a1 : a0, dy, dx);
            float py = (hofp[p] + khf) + dy;
            float px = (wof + kwf) + dx;
            int y0 = __float2int_rd(py);
            int x0 = __float2int_rd(px);
            float wy = py - (float)y0;
            float wx = px - (float)x0;

            // 5-op bilinear coefs: m=wy*wx; c10=wy-m; c01=wx-m; c00=(1-wy)-c01
            float m   = wy * wx;
            float c10 = wy - m;
            float c01 = wx - m;
            float c00 = (1.f - wy) - c01;
            float c11 = m;

            int ly0 = y0 - rowBase;
            int lx0 = x0 - colBase;

            if ((unsigned)ly0 <= TH - 2 && (unsigned)lx0 <= TW - 2) {
                // fast path: zero-filled tile makes validity masks redundant
                int t = ly0 * TW + lx0;
                {
                    const float* __restrict__ tc = &s_tile[t];
                    vch[p][0] = fmaf(c11, tc[TW + 1], fmaf(c10, tc[TW], fmaf(c01, tc[1], c00 * tc[0])));
                }
                {
                    const float* __restrict__ tc = &s_tile[TILE_CH + t];
                    vch[p][1] = fmaf(c11, tc[TW + 1], fmaf(c10, tc[TW], fmaf(c01, tc[1], c00 * tc[0])));
                }
                {
                    const float* __restrict__ tc = &s_tile[2 * TILE_CH + t];
                    vch[p][2] = fmaf(c11, tc[TW + 1], fmaf(c10, tc[TW], fmaf(c01, tc[1], c00 * tc[0])));
                }
            } else {
                // rare slow path: clamped global loads (exact reference semantics)
                bool vy0 = (y0 >= 0)  && (y0 <= IH - 1);
                bool vy1 = (y0 >= -1) && (y0 <= IH - 2);
                bool vx0 = (x0 >= 0)  && (x0 <= IW - 1);
                bool vx1 = (x0 >= -1) && (x0 <= IW - 2);
                float m00 = c00 * ((vy0 && vx0) ? 1.f : 0.f);
                float m01 = c01 * ((vy0 && vx1) ? 1.f : 0.f);
                float m10 = c10 * ((vy1 && vx0) ? 1.f : 0.f);
                float m11 = c11 * ((vy1 && vx1) ? 1.f : 0.f);
                int yc0 = min(max(y0, 0), IH - 1);
                int yc1 = min(max(y0 + 1, 0), IH - 1);
                int xc0 = min(max(x0, 0), IW - 1);
                int xc1 = min(max(x0 + 1, 0), IW - 1);
                int i00 = yc0 * IW + xc0;
                int i01 = yc0 * IW + xc1;
                int i10 = yc1 * IW + xc0;
                int i11 = yc1 * IW + xc1;
#pragma unroll
                for (int c = 0; c < 3; c++) {
                    const float* __restrict__ xc = xb + (size_t)c * IH * IW;
                    vch[p][c] = m00 * __ldg(xc + i00) + m01 * __ldg(xc + i01)
                              + m10 * __ldg(xc + i10) + m11 * __ldg(xc + i11);
                }
            }
        }

        // ---- packed einsum: acc[o] += dup(w2[o][c][kk]) * (v_p0, v_p1) ----
#pragma unroll
        for (int c = 0; c < 3; c++) {
            u64 vp = pack2(vch[0][c], vch[1][c]);
            accp[0] = fma2(w2v[c * 3 + 0], vp, accp[0]);
            accp[1] = fma2(w2v[c * 3 + 1], vp, accp[1]);
            accp[2] = fma2(w2v[c * 3 + 2], vp, accp[2]);
        }
    }

    // ---- store (streaming: output is write-once) ----
    if (wo < WO) {
        const size_t plane = (size_t)HO * WO;
        const size_t base  = (size_t)b * 3 * plane + (size_t)hoA * WO + wo;
        float a0, a1;
#pragma unroll
        for (int o = 0; o < 3; o++) {
            unpack2(accp[o], a0, a1);
            if (hoA < HO)     __stcs(&out[base + o * plane],      a0);
            if (hoA + 1 < HO) __stcs(&out[base + o * plane + WO], a1);
        }
    }
}

extern "C" void kernel_launch(void* const* d_in, const int* in_sizes, int n_in,
                              void* d_out, int out_size)
{
    const float* x  = (const float*)d_in[0];
    const float* w1 = (const float*)d_in[1];
    const float* b1 = (const float*)d_in[2];
    const float* w2 = (const float*)d_in[3];
    const float* b2 = (const float*)d_in[4];
    float* out = (float*)d_out;

    // 1) pack weights into __device__ scratch
    pack_weights<<<1, 256>>>(w1, b1, w2, b2);

    // 2) install into __constant__ (device-to-device async copy; graph-capturable)
    void* gaddr = nullptr;
    cudaGetSymbolAddress(&gaddr, g_pack);
    cudaMemcpyToSymbolAsync(c_pack, gaddr, sizeof(WPack), 0,
                            cudaMemcpyDeviceToDevice, 0);

    // 3) main kernel
    dim3 block(32, 8, 1);
    dim3 grid((WO + 31) / 32, (HO + BROWS - 1) / BROWS, NB);
    deform_fused16<<<grid, block>>>(x, out);
}

// round 17
// speedup vs baseline: 1.0780x; 1.0037x over previous
#include <cuda_runtime.h>

#define IH 384
#define IW 384
#define HO 382
#define WO 382
#define NB 8
#define HALOY 6
#define HALOX 8
#define BROWS 8        // pixel rows per block
#define TH 22          // rows [ho0-6, ho0+15]
#define TW 48          // cols [wo0-8, wo0+39], 12 float4 per row, 16B-aligned
#define TILE_CH (TH * TW)   // 1056

typedef unsigned long long u64;

__device__ __forceinline__ u64 fma2(u64 a, u64 b, u64 c) {
    u64 d;
    asm("fma.rn.f32x2 %0, %1, %2, %3;" : "=l"(d) : "l"(a), "l"(b), "l"(c));
    return d;
}
__device__ __forceinline__ u64 add2(u64 a, u64 b) {
    u64 d;
    asm("add.rn.f32x2 %0, %1, %2;" : "=l"(d) : "l"(a), "l"(b));
    return d;
}
__device__ __forceinline__ u64 pack2(float lo, float hi) {
    u64 r;
    asm("mov.b64 %0, {%1, %2};" : "=l"(r) : "f"(lo), "f"(hi));
    return r;
}
__device__ __forceinline__ void unpack2(u64 v, float& lo, float& hi) {
    asm("mov.b64 {%0, %1}, %2;" : "=f"(lo), "=f"(hi) : "l"(v));
}

struct __align__(16) WPack {
    u64 w1p[9 * 28];   // [kk][j] packed (wdy, wdx); slot 27 unused; 224B/kk
    u64 b1p[9];        // packed (b_dy, b_dx)
    u64 pad1;
    u64 w2d[9 * 10];   // [kk][c*3+o] = dup(w2[o][c][kk]); slot 9 = 0 pad
    u64 b2d[3];        // dup(b2[o])
    u64 pad2;
};

__device__   WPack g_pack;
__constant__ WPack c_pack;

__global__ void pack_weights(const float* __restrict__ w1,
                             const float* __restrict__ b1,
                             const float* __restrict__ w2,
                             const float* __restrict__ b2)
{
    int i = threadIdx.x;
    if (i < 9 * 27) {
        int kk = i / 27, j = i % 27;
        g_pack.w1p[kk * 28 + j] = pack2(w1[(2 * kk) * 27 + j], w1[(2 * kk + 1) * 27 + j]);
    }
    if (i < 9) {
        g_pack.w1p[i * 28 + 27] = 0ull;
        g_pack.b1p[i] = pack2(b1[2 * i], b1[2 * i + 1]);
        g_pack.w2d[i * 10 + 9] = 0ull;
    }
    if (i < 81) {
        int kk = i / 9, r = i % 9;
        int c = r / 3, o = r % 3;
        float v = w2[o * 27 + c * 9 + kk];
        g_pack.w2d[kk * 10 + c * 3 + o] = pack2(v, v);
    }
    if (i < 3) { float v = b2[i]; g_pack.b2d[i] = pack2(v, v); }
    if (i == 0) { g_pack.pad1 = 0ull; g_pack.pad2 = 0ull; }
}

__global__ __launch_bounds__(128, 7)
void deform_fused17(const float* __restrict__ x,
                    float* __restrict__ out)
{
    __shared__ __align__(16) float s_tile[3 * TILE_CH];

    const int tid = threadIdx.y * 32 + threadIdx.x;

    const int wo0 = blockIdx.x * 32;
    const int ho0 = blockIdx.y * BROWS;
    const int b   = blockIdx.z;
    const float* __restrict__ xb = x + (size_t)b * 3 * IH * IW;

    const int rowBase = ho0 - HALOY;
    const int colBase = wo0 - HALOX;   // divisible by 4 -> 16B aligned

    // ---- input tile to shared, vectorized float4 (zero-filled outside image) ----
    for (int i = tid; i < 3 * TH * (TW / 4); i += 128) {
        int c  = i / (TH * (TW / 4));
        int rr = i - c * (TH * (TW / 4));
        int r  = rr / (TW / 4);
        int q  = rr - r * (TW / 4);
        int gy  = rowBase + r;
        int gx0 = colBase + 4 * q;
        float4 v = make_float4(0.f, 0.f, 0.f, 0.f);
        if ((unsigned)gy < IH) {
            const float* rp = xb + ((size_t)c * IH + gy) * IW;
            if (gx0 >= 0 && gx0 + 3 < IW) {
                v = __ldg((const float4*)(rp + gx0));   // aligned LDG.128
            } else {
                float t0 = ((unsigned)(gx0 + 0) < IW) ? __ldg(rp + gx0 + 0) : 0.f;
                float t1 = ((unsigned)(gx0 + 1) < IW) ? __ldg(rp + gx0 + 1) : 0.f;
                float t2 = ((unsigned)(gx0 + 2) < IW) ? __ldg(rp + gx0 + 2) : 0.f;
                float t3 = ((unsigned)(gx0 + 3) < IW) ? __ldg(rp + gx0 + 3) : 0.f;
                v = make_float4(t0, t1, t2, t3);
            }
        }
        *(float4*)&s_tile[c * TILE_CH + r * TW + 4 * q] = v;   // STS.128
    }
    __syncthreads();

    const int wo  = wo0 + threadIdx.x;
    const int hoA = ho0 + 2 * threadIdx.y;   // pixel pair rows hoA, hoA+1 (ty 0..3)
    const int ltx = threadIdx.x + HALOX;
    const int lty = 2 * threadIdx.y + HALOY;

    // float coordinate bases (hoisted I2F)
    const float hofp[2] = { (float)hoA, (float)hoA + 1.f };
    const float wof     = (float)wo;

    // ---- window (4 rows x 3 cols x 3 ch) duplicated-packed in registers ----
    u64 wr2[3][4][3];
#pragma unroll
    for (int c = 0; c < 3; c++)
#pragma unroll
        for (int r = 0; r < 4; r++)
#pragma unroll
            for (int kw = 0; kw < 3; kw++) {
                float v = s_tile[c * TILE_CH + (lty + r) * TW + (ltx + kw)];
                wr2[c][r][kw] = pack2(v, v);
            }

    // packed (p0, p1) accumulators per output channel
    u64 accp[3];
#pragma unroll
    for (int o = 0; o < 3; o++) accp[o] = c_pack.b2d[o];

#pragma unroll
    for (int kk = 0; kk < 9; kk++) {
        // ---- offset conv: 13 paired LDCU.128 + 1 scalar tail; 4 FFMA2 chains ----
        u64 a0a = c_pack.b1p[kk];
        u64 a1a = a0a;
        u64 a0b = pack2(0.f, 0.f);
        u64 a1b = a0b;
        const ulonglong2* __restrict__ wq = (const ulonglong2*)&c_pack.w1p[kk * 28];
#pragma unroll
        for (int jj = 0; jj < 13; jj++) {
            ulonglong2 w = wq[jj];
            {
                const int j = 2 * jj;
                const int c = j / 9, kh = (j / 3) % 3, kw = j % 3;
                a0a = fma2(wr2[c][kh][kw],     w.x, a0a);
                a1a = fma2(wr2[c][kh + 1][kw], w.x, a1a);
            }
            {
                const int j = 2 * jj + 1;
                const int c = j / 9, kh = (j / 3) % 3, kw = j % 3;
                a0b = fma2(wr2[c][kh][kw],     w.y, a0b);
                a1b = fma2(wr2[c][kh + 1][kw], w.y, a1b);
            }
        }
        {
            // tail j = 26  (c=2, kh=2, kw=2)
            u64 w26 = c_pack.w1p[kk * 28 + 26];
            a0a = fma2(wr2[2][2][2], w26, a0a);
            a1a = fma2(wr2[2][3][2], w26, a1a);
        }
        u64 a0 = add2(a0a, a0b);
        u64 a1 = add2(a1a, a1b);

        const int kh = kk / 3;
        const int kw = kk - 3 * kh;
        const float khf = (float)kh;   // compile-time under full unroll
        const float kwf = (float)kw;

        // dup'd w2 for this kk via LDCU.128 (paired loads cover 9 weights + pad)
        u64 w2v[9];
        {
            const ulonglong2* __restrict__ w2q = (const ulonglong2*)&c_pack.w2d[kk * 10];
            ulonglong2 t0 = w2q[0], t1 = w2q[1], t2 = w2q[2], t3 = w2q[3];
            w2v[0] = t0.x; w2v[1] = t0.y;
            w2v[2] = t1.x; w2v[3] = t1.y;
            w2v[4] = t2.x; w2v[5] = t2.y;
            w2v[6] = t3.x; w2v[7] = t3.y;
            w2v[8] = c_pack.w2d[kk * 10 + 8];
        }

        float vch[2][3];
#pragma unroll
        for (int p = 0; p < 2; p++) {
            float dy, dx;
            unpack2(p ? a1 : a0, dy, dx);
            float py = (hofp[p] + khf) + dy;
            float px = (wof + kwf) + dx;
            int y0 = __float2int_rd(py);
            int x0 = __float2int_rd(px);
            float wy = py - (float)y0;
            float wx = px - (float)x0;

            // 5-op bilinear coefs
            float m   = wy * wx;
            float c10 = wy - m;
            float c01 = wx - m;
            float c00 = (1.f - wy) - c01;
            float c11 = m;

            int ly0 = y0 - rowBase;
            int lx0 = x0 - colBase;

            if ((unsigned)ly0 <= TH - 2 && (unsigned)lx0 <= TW - 2) {
                // fast path: zero-filled tile makes validity masks redundant
                int t = ly0 * TW + lx0;
                {
                    const float* __restrict__ tc = &s_tile[t];
                    vch[p][0] = fmaf(c11, tc[TW + 1], fmaf(c10, tc[TW], fmaf(c01, tc[1], c00 * tc[0])));
                }
                {
                    const float* __restrict__ tc = &s_tile[TILE_CH + t];
                    vch[p][1] = fmaf(c11, tc[TW + 1], fmaf(c10, tc[TW], fmaf(c01, tc[1], c00 * tc[0])));
                }
                {
                    const float* __restrict__ tc = &s_tile[2 * TILE_CH + t];
                    vch[p][2] = fmaf(c11, tc[TW + 1], fmaf(c10, tc[TW], fmaf(c01, tc[1], c00 * tc[0])));
                }
            } else {
                // rare slow path: clamped global loads (exact reference semantics)
                bool vy0 = (y0 >= 0)  && (y0 <= IH - 1);
                bool vy1 = (y0 >= -1) && (y0 <= IH - 2);
                bool vx0 = (x0 >= 0)  && (x0 <= IW - 1);
                bool vx1 = (x0 >= -1) && (x0 <= IW - 2);
                float m00 = c00 * ((vy0 && vx0) ? 1.f : 0.f);
                float m01 = c01 * ((vy0 && vx1) ? 1.f : 0.f);
                float m10 = c10 * ((vy1 && vx0) ? 1.f : 0.f);
                float m11 = c11 * ((vy1 && vx1) ? 1.f : 0.f);
                int yc0 = min(max(y0, 0), IH - 1);
                int yc1 = min(max(y0 + 1, 0), IH - 1);
                int xc0 = min(max(x0, 0), IW - 1);
                int xc1 = min(max(x0 + 1, 0), IW - 1);
                int i00 = yc0 * IW + xc0;
                int i01 = yc0 * IW + xc1;
                int i10 = yc1 * IW + xc0;
                int i11 = yc1 * IW + xc1;
#pragma unroll
                for (int c = 0; c < 3; c++) {
                    const float* __restrict__ xc = xb + (size_t)c * IH * IW;
                    vch[p][c] = m00 * __ldg(xc + i00) + m01 * __ldg(xc + i01)
                              + m10 * __ldg(xc + i10) + m11 * __ldg(xc + i11);
                }
            }
        }

        // ---- packed einsum: acc[o] += dup(w2[o][c][kk]) * (v_p0, v_p1) ----
#pragma unroll
        for (int c = 0; c < 3; c++) {
            u64 vp = pack2(vch[0][c], vch[1][c]);
            accp[0] = fma2(w2v[c * 3 + 0], vp, accp[0]);
            accp[1] = fma2(w2v[c * 3 + 1], vp, accp[1]);
            accp[2] = fma2(w2v[c * 3 + 2], vp, accp[2]);
        }
    }

    // ---- store (streaming: output is write-once) ----
    if (wo < WO) {
        const size_t plane = (size_t)HO * WO;
        const size_t base  = (size_t)b * 3 * plane + (size_t)hoA * WO + wo;
        float a0, a1;
#pragma unroll
        for (int o = 0; o < 3; o++) {
            unpack2(accp[o], a0, a1);
            if (hoA < HO)     __stcs(&out[base + o * plane],      a0);
            if (hoA + 1 < HO) __stcs(&out[base + o * plane + WO], a1);
        }
    }
}

extern "C" void kernel_launch(void* const* d_in, const int* in_sizes, int n_in,
                              void* d_out, int out_size)
{
    const float* x  = (const float*)d_in[0];
    const float* w1 = (const float*)d_in[1];
    const float* b1 = (const float*)d_in[2];
    const float* w2 = (const float*)d_in[3];
    const float* b2 = (const float*)d_in[4];
    float* out = (float*)d_out;

    // 1) pack weights into __device__ scratch
    pack_weights<<<1, 256>>>(w1, b1, w2, b2);

    // 2) install into __constant__ (device-to-device async copy; graph-capturable)
    void* gaddr = nullptr;
    cudaGetSymbolAddress(&gaddr, g_pack);
    cudaMemcpyToSymbolAsync(c_pack, gaddr, sizeof(WPack), 0,
                            cudaMemcpyDeviceToDevice, 0);

    // 3) main kernel
    dim3 block(32, 4, 1);
    dim3 grid((WO + 31) / 32, (HO + BROWS - 1) / BROWS, NB);
    deform_fused17<<<grid, block>>>(x, out);
}